// round 11
// baseline (speedup 1.0000x reference)
#include <cuda_runtime.h>
#include <cuda_fp16.h>
#include <cstdint>

// Problem constants
#define NPIX   16384            // B*H*W
#define NCODE  1024             // N (= K of the GEMM)
#define DDIM   256              // D (= M of the GEMM)
#define ZQ_SIZE 4194304         // B*D*H*W
#define KL_OFF  ZQ_SIZE
#define IDX_OFF (ZQ_SIZE + 1)
#define PERP_OFF (ZQ_SIZE + 1 + NPIX)

// Static device scratch (no allocation allowed).
// INVARIANT: g_avg / g_kl are zero at kernel_launch entry; the gemm finalize
// resets them after reading, so every execution restores the invariant.
__device__ __half g_sampleH[(size_t)NPIX * NCODE];  // 32 MB, [pixel][k]
__device__ __half g_cbH[(size_t)DDIM * NCODE];      // 512 KB, [d][k] (transposed)
__device__ float g_avg[NCODE];
__device__ float g_kl;

// ---------------------------------------------------------------- helpers
__device__ __forceinline__ uint32_t smem_u32(const void* p) {
    uint32_t a;
    asm("{ .reg .u64 t; cvta.to.shared.u64 t, %1; cvt.u32.u64 %0, t; }" : "=r"(a) : "l"(p));
    return a;
}
__device__ __forceinline__ void cpa16(uint32_t d, const void* s) {
    asm volatile("cp.async.cg.shared.global [%0], [%1], 16;" :: "r"(d), "l"(s));
}
__device__ __forceinline__ void ldsm4(uint32_t* r, uint32_t a) {
    asm volatile("ldmatrix.sync.aligned.m8n8.x4.shared.b16 {%0,%1,%2,%3}, [%4];"
                 : "=r"(r[0]), "=r"(r[1]), "=r"(r[2]), "=r"(r[3]) : "r"(a));
}
__device__ __forceinline__ void mma_f16(float* c, const uint32_t* a, const uint32_t* b) {
    asm volatile(
        "mma.sync.aligned.m16n8k16.row.col.f32.f16.f16.f32 "
        "{%0,%1,%2,%3}, {%4,%5,%6,%7}, {%8,%9}, {%0,%1,%2,%3};"
        : "+f"(c[0]), "+f"(c[1]), "+f"(c[2]), "+f"(c[3])
        : "r"(a[0]), "r"(a[1]), "r"(a[2]), "r"(a[3]), "r"(b[0]), "r"(b[1]));
}

// Branch-free fused lgamma + digamma for x >= 1 (double shift + Stirling at x+2).
// Single MUFU reciprocal; trimmed series (err < 6e-6 at x2 >= 3).
__device__ __forceinline__ void lgamma_digamma(float x, float& lg, float& ps) {
    float prod = x * (x + 1.f);
    float x2   = x + 2.f;
    float invall = __fdividef(1.f, prod * x2);
    float inv  = invall * prod;      // 1/(x+2)
    float invp = invall * x2;        // 1/(x(x+1))
    float lx   = __logf(x2);
    float inv2 = inv * inv;
    lg = (x2 - 0.5f) * lx - x2 + 0.9189385332046727f
       + inv * (0.083333333333f - inv2 * 2.7777777778e-3f)
       - __logf(prod);
    ps = lx - 0.5f * inv
       - inv2 * (0.083333333333f - inv2 * 8.3333333333e-3f)
       - (2.f * x + 1.f) * invp;
}

// ---------------------------------------------------------------- per-pixel pass
// 1024 blocks x 512 threads, 2 CTAs/SM forced (scalar body fits 64 regs).
// Blocks 0..255 first transpose one 32x32 codebook tile (gemm launches after
// this kernel completes, so ordering is guaranteed).
// t = alpha/(-log u); softmax(T=0.5) == t^2 / sum t^2; argmax(t) == argmax.
#define PXS 1025
extern __shared__ float smem_dyn[];
__global__ __launch_bounds__(512, 2) void pixel_kernel(
    const float* __restrict__ logits,
    const float* __restrict__ noise,
    const float* __restrict__ cb,
    float* __restrict__ out)
{
    float* alpha_t = smem_dyn;              // [16][PXS]
    const int tid = threadIdx.x;
    const int blk = blockIdx.x;             // b*64 + h*2 + half
    const int b = blk >> 6, h = (blk >> 1) & 31, half = blk & 1;
    const int w0 = half * 16;

    // Codebook transpose pre-phase (blocks 0..255, one 32x32 tile each)
    if (blk < 256) {
        float (*tt)[33] = (float(*)[33])smem_dyn;
        const int n0 = (blk & 31) * 32, d0 = (blk >> 5) * 32;
        const int x = tid & 31, y = tid >> 5;       // y in 0..15
        #pragma unroll
        for (int j = 0; j < 2; j++) {
            int r = y + j * 16;
            tt[r][x] = cb[(size_t)(n0 + r) * DDIM + d0 + x];
        }
        __syncthreads();
        #pragma unroll
        for (int j = 0; j < 2; j++) {
            int r = y + j * 16;
            g_cbH[(size_t)(d0 + r) * NCODE + n0 + x] = __float2half_rn(tt[x][r]);
        }
        __syncthreads();
    }

    // Stage: softplus(logits)+1, transposed to [w][n]
    const float* lg = logits + (size_t)b * (NCODE * 1024) + (size_t)h * 32 + w0;
    #pragma unroll 4
    for (int i = tid; i < 16 * NCODE; i += 512) {
        int n = i >> 4, w = i & 15;
        float x = lg[(size_t)n * 1024 + w];
        float e = __expf(-fabsf(x));
        float sp = fmaxf(x, 0.f) + __logf(1.f + e);
        alpha_t[w * PXS + n] = sp + 1.f;
    }
    __syncthreads();

    const int warp = tid >> 5, lane = tid & 31;      // warp = pixel-in-block
    const int p = b * 1024 + h * 32 + w0 + warp;     // global pixel index
    float* row = alpha_t + warp * PXS;
    const float* nz = noise + (size_t)p * NCODE;

    // Pass 1: KL sums, t = a / (-log u), Z = sum t^2, argmax t
    float S = 0.f, slg = 0.f, sdg = 0.f, Z = 0.f, m = -1.f;
    int bi = 0;
    #pragma unroll 4
    for (int k = 0; k < 32; k++) {
        int n = k * 32 + lane;
        float a = row[n];
        float lga, psa;
        lgamma_digamma(a, lga, psa);
        S += a; slg += lga; sdg += (a - 1.f) * psa;
        float L = -__logf(nz[n]);
        float t = __fdividef(a, L);
        row[n] = t;
        Z += t * t;
        if (t > m) { m = t; bi = n; }
    }
    #pragma unroll
    for (int o = 16; o; o >>= 1) {
        S   += __shfl_xor_sync(0xffffffffu, S, o);
        slg += __shfl_xor_sync(0xffffffffu, slg, o);
        sdg += __shfl_xor_sync(0xffffffffu, sdg, o);
        Z   += __shfl_xor_sync(0xffffffffu, Z, o);
        float mo = __shfl_xor_sync(0xffffffffu, m, o);
        int   bo = __shfl_xor_sync(0xffffffffu, bi, o);
        if (mo > m || (mo == m && bo < bi)) { m = mo; bi = bo; }
    }
    float invZ = __fdividef(1.f, Z);

    // Pass 2: normalized sample -> fp16 global + fp32 smem (for column sums)
    __half* srow = g_sampleH + (size_t)p * NCODE;
    #pragma unroll 4
    for (int k = 0; k < 32; k++) {
        int n = k * 32 + lane;
        float t = row[n];
        float s = t * t * invZ;
        row[n] = s;
        srow[n] = __float2half_rn(s);
    }

    if (lane == 0) {
        float lgS, psS, lgN, psN;
        lgamma_digamma(S, lgS, psS);
        lgamma_digamma(1024.f, lgN, psN);
        float kl = lgS - slg - lgN + sdg - (S - 1024.f) * psS;
        atomicAdd(&g_kl, kl);
        out[IDX_OFF + p] = (float)bi;
    }
    __syncthreads();

    // Column sums over the 16 pixels -> one atomic per code per block
    #pragma unroll
    for (int c = tid; c < NCODE; c += 512) {
        float acc = 0.f;
        #pragma unroll
        for (int w = 0; w < 16; w++) acc += alpha_t[w * PXS + c];
        atomicAdd(&g_avg[c], acc);
    }
}

// ---------------------------------------------------------------- fp16 mma GEMM
// C[d-tile 128][p-tile 128] = sum_k cbT[d][k] * sample[p][k]
// 8 warps: wm=warp>>2 (x64), wn=warp&3 (x32). K-tile 32, 4-stage cp.async
// (wait_group 2 -> two full stages in flight to cover DRAM latency).
// Row stride 80B: 20r mod 32 covers all banks -> conflict-free ldmatrix.
// Block (0,0) computes kl/perplexity, then RESETS g_avg/g_kl for next replay.
#define KT        32
#define ROWB      80                       // bytes per smem row
#define STG_BYTES (128 * ROWB)             // 10240 per operand per stage
#define NSTAGE    4
#define GEMM_SMEM (2 * NSTAGE * STG_BYTES) // 81920

__device__ __forceinline__ void gemm_issue(uint32_t Ab, uint32_t Bb,
                                           const __half* arow, const __half* brow,
                                           int k0, int tid) {
    const int row = tid >> 1, c0 = (tid & 1) * 2;     // 2 chunks each of A,B
    #pragma unroll
    for (int j = 0; j < 2; j++) {
        cpa16(Ab + row * ROWB + (c0 + j) * 16, arow + (size_t)row * NCODE + k0 + (c0 + j) * 8);
        cpa16(Bb + row * ROWB + (c0 + j) * 16, brow + (size_t)row * NCODE + k0 + (c0 + j) * 8);
    }
    asm volatile("cp.async.commit_group;" ::: "memory");
}

__global__ __launch_bounds__(256, 2) void gemm_mma(float* __restrict__ out) {
    extern __shared__ __align__(16) char gsm[];
    const uint32_t base = smem_u32(gsm);

    const int tid = threadIdx.x, warp = tid >> 5, lane = tid & 31;
    const int gid = lane >> 2, tig = lane & 3;
    const int wm = warp >> 2, wn = warp & 3;
    const int p0 = blockIdx.x * 128, d0 = blockIdx.y * 128;

    const __half* arow = g_cbH + (size_t)d0 * NCODE;
    const __half* brow = g_sampleH + (size_t)p0 * NCODE;

    // lane-fixed ldmatrix address components
    const uint32_t a_lrow = (uint32_t)(wm * 64 + (lane & 15)) * ROWB + ((lane >> 4) & 1) * 16;
    const uint32_t b_lrow = (uint32_t)(wn * 32 + ((lane >> 4) & 1) * 8 + (lane & 7)) * ROWB
                          + ((lane >> 3) & 1) * 16;

    // Prologue: stages 0,1,2 in flight
    #pragma unroll
    for (int s = 0; s < 3; s++)
        gemm_issue(base + s * STG_BYTES, base + (NSTAGE + s) * STG_BYTES,
                   arow, brow, s * KT, tid);

    float acc[4][4][4] = {};

    for (int c = 0; c < 32; c++) {
        const int buf = c & 3;
        // stage c must be complete; up to 2 younger stages may stay in flight
        if (c < 30)      asm volatile("cp.async.wait_group 2;" ::: "memory");
        else if (c == 30) asm volatile("cp.async.wait_group 1;" ::: "memory");
        else              asm volatile("cp.async.wait_group 0;" ::: "memory");
        __syncthreads();
        if (c + 3 < 32) {
            const int nb = (c + 3) & 3;
            gemm_issue(base + nb * STG_BYTES, base + (NSTAGE + nb) * STG_BYTES,
                       arow, brow, (c + 3) * KT, tid);
        }

        const uint32_t Ab = base + buf * STG_BYTES + a_lrow;
        const uint32_t Bb = base + (NSTAGE + buf) * STG_BYTES + b_lrow;
        #pragma unroll
        for (int sk = 0; sk < 2; sk++) {
            const uint32_t ko = sk * 32;
            uint32_t afr[4][4], bfr[4][2];
            #pragma unroll
            for (int mf = 0; mf < 4; mf++)
                ldsm4(afr[mf], Ab + mf * (16 * ROWB) + ko);
            #pragma unroll
            for (int np = 0; np < 2; np++) {
                uint32_t r[4];
                ldsm4(r, Bb + np * (16 * ROWB) + ko);
                bfr[2 * np][0] = r[0]; bfr[2 * np][1] = r[1];
                bfr[2 * np + 1][0] = r[2]; bfr[2 * np + 1][1] = r[3];
            }
            #pragma unroll
            for (int mf = 0; mf < 4; mf++)
                #pragma unroll
                for (int nf = 0; nf < 4; nf++)
                    mma_f16(acc[mf][nf], afr[mf], bfr[nf]);
        }
        __syncthreads();
    }

    const int bimg = p0 >> 10, hwb = p0 & 1023;
    #pragma unroll
    for (int mf = 0; mf < 4; mf++) {
        const int d = d0 + wm * 64 + mf * 16 + gid;
        float* orow = out + (size_t)bimg * (DDIM * 1024) + (size_t)d * 1024 + hwb;
        #pragma unroll
        for (int nf = 0; nf < 4; nf++) {
            const int col = wn * 32 + nf * 8 + 2 * tig;
            *(float2*)&orow[col]            = make_float2(acc[mf][nf][0], acc[mf][nf][1]);
            *(float2*)&orow[col + 8 * 1024] = make_float2(acc[mf][nf][2], acc[mf][nf][3]);
        }
    }

    // Fused finalize: g_avg/g_kl complete (pixel_kernel precedes this kernel).
    // After reading, reset them to preserve the zero-on-entry invariant.
    if (blockIdx.x == 0 && blockIdx.y == 0) {
        __shared__ float red[8];
        float hs = 0.f;
        #pragma unroll
        for (int j = 0; j < 4; j++) {
            float v = g_avg[tid * 4 + j] * (1.f / 16384.f);
            hs += v * __logf(v + 1e-10f);
        }
        *(float4*)&g_avg[tid * 4] = make_float4(0.f, 0.f, 0.f, 0.f);  // reset
        #pragma unroll
        for (int o = 16; o; o >>= 1) hs += __shfl_xor_sync(0xffffffffu, hs, o);
        if (lane == 0) red[warp] = hs;
        __syncthreads();
        if (tid == 0) {
            float s = 0.f;
            #pragma unroll
            for (int wq = 0; wq < 8; wq++) s += red[wq];
            out[PERP_OFF] = __expf(-s);
            out[KL_OFF] = (1e-3f / 16384.f) * g_kl;
            g_kl = 0.f;                                               // reset
        }
    }
}

// ---------------------------------------------------------------- launch
extern "C" void kernel_launch(void* const* d_in, const int* in_sizes, int n_in,
                              void* d_out, int out_size) {
    const float* logits = (const float*)d_in[0];
    const float* cb     = (const float*)d_in[1];
    const float* noise  = (const float*)d_in[2];
    float* out = (float*)d_out;

    const int px_smem = 16 * PXS * 4;
    cudaFuncSetAttribute(pixel_kernel,
                         cudaFuncAttributeMaxDynamicSharedMemorySize, px_smem);
    cudaFuncSetAttribute(gemm_mma,
                         cudaFuncAttributeMaxDynamicSharedMemorySize, GEMM_SMEM);

    pixel_kernel<<<1024, 512, px_smem>>>(logits, noise, cb, out);
    gemm_mma<<<dim3(NPIX / 128, DDIM / 128), 256, GEMM_SMEM>>>(out);
}

// round 12
// speedup vs baseline: 1.0081x; 1.0081x over previous
#include <cuda_runtime.h>
#include <cuda_fp16.h>
#include <cstdint>

// Problem constants
#define NPIX   16384            // B*H*W
#define NCODE  1024             // N (= K of the GEMM)
#define DDIM   256              // D (= M of the GEMM)
#define ZQ_SIZE 4194304         // B*D*H*W
#define KL_OFF  ZQ_SIZE
#define IDX_OFF (ZQ_SIZE + 1)
#define PERP_OFF (ZQ_SIZE + 1 + NPIX)

// Static device scratch (no allocation allowed).
// INVARIANT: g_avg / g_kl are zero at kernel_launch entry; the gemm finalize
// resets them after reading, so every execution restores the invariant.
__device__ __half g_sampleH[(size_t)NPIX * NCODE];  // 32 MB, [pixel][k]
__device__ __half g_cbH[(size_t)DDIM * NCODE];      // 512 KB, [d][k] (transposed)
__device__ float g_avg[NCODE];
__device__ float g_kl;

// ---------------------------------------------------------------- helpers
__device__ __forceinline__ uint32_t smem_u32(const void* p) {
    uint32_t a;
    asm("{ .reg .u64 t; cvta.to.shared.u64 t, %1; cvt.u32.u64 %0, t; }" : "=r"(a) : "l"(p));
    return a;
}
__device__ __forceinline__ void cpa16(uint32_t d, const void* s) {
    asm volatile("cp.async.cg.shared.global [%0], [%1], 16;" :: "r"(d), "l"(s));
}
__device__ __forceinline__ void ldsm4(uint32_t* r, uint32_t a) {
    asm volatile("ldmatrix.sync.aligned.m8n8.x4.shared.b16 {%0,%1,%2,%3}, [%4];"
                 : "=r"(r[0]), "=r"(r[1]), "=r"(r[2]), "=r"(r[3]) : "r"(a));
}
__device__ __forceinline__ void mma_f16(float* c, const uint32_t* a, const uint32_t* b) {
    asm volatile(
        "mma.sync.aligned.m16n8k16.row.col.f32.f16.f16.f32 "
        "{%0,%1,%2,%3}, {%4,%5,%6,%7}, {%8,%9}, {%0,%1,%2,%3};"
        : "+f"(c[0]), "+f"(c[1]), "+f"(c[2]), "+f"(c[3])
        : "r"(a[0]), "r"(a[1]), "r"(a[2]), "r"(a[3]), "r"(b[0]), "r"(b[1]));
}

// Full fused lgamma + digamma (used only for the per-pixel S / constant tails).
__device__ __forceinline__ void lgamma_digamma(float x, float& lg, float& ps) {
    float prod = x * (x + 1.f);
    float x2   = x + 2.f;
    float invall = __fdividef(1.f, prod * x2);
    float inv  = invall * prod;      // 1/(x+2)
    float invp = invall * x2;        // 1/(x(x+1))
    float lx   = __logf(x2);
    float inv2 = inv * inv;
    lg = (x2 - 0.5f) * lx - x2 + 0.9189385332046727f
       + inv * (0.083333333333f - inv2 * 2.7777777778e-3f)
       - __logf(prod);
    ps = lx - 0.5f * inv
       - inv2 * (0.083333333333f - inv2 * 8.3333333333e-3f)
       - (2.f * x + 1.f) * invp;
}

// ---------------------------------------------------------------- per-pixel pass
// 1024 blocks x 512 threads. Block = 16 pixels.
// Blocks 0..255 first transpose one 32x32 codebook tile.
// t = alpha/(-log u); softmax(T=0.5) == t^2 / sum t^2; argmax(t^2) == argmax.
// The -log(prod) part of lgamma is batched: one log per 4 elements via the
// product Pi(prod_i) (prod in [2,56], 56^4 < 1e7 -> exact-ish fp32).
#define PXS 1025
extern __shared__ float smem_dyn[];
__global__ __launch_bounds__(512) void pixel_kernel(
    const float* __restrict__ logits,
    const float* __restrict__ noise,
    const float* __restrict__ cb,
    float* __restrict__ out)
{
    float* alpha_t = smem_dyn;              // [16][PXS]
    const int tid = threadIdx.x;
    const int blk = blockIdx.x;             // b*64 + h*2 + half
    const int b = blk >> 6, h = (blk >> 1) & 31, half = blk & 1;
    const int w0 = half * 16;

    // Codebook transpose pre-phase (blocks 0..255, one 32x32 tile each)
    if (blk < 256) {
        float (*tt)[33] = (float(*)[33])smem_dyn;
        const int n0 = (blk & 31) * 32, d0 = (blk >> 5) * 32;
        const int x = tid & 31, y = tid >> 5;       // y in 0..15
        #pragma unroll
        for (int j = 0; j < 2; j++) {
            int r = y + j * 16;
            tt[r][x] = cb[(size_t)(n0 + r) * DDIM + d0 + x];
        }
        __syncthreads();
        #pragma unroll
        for (int j = 0; j < 2; j++) {
            int r = y + j * 16;
            g_cbH[(size_t)(d0 + r) * NCODE + n0 + x] = __float2half_rn(tt[x][r]);
        }
        __syncthreads();
    }

    // Stage: softplus(logits)+1, transposed to [w][n]
    const float* lg = logits + (size_t)b * (NCODE * 1024) + (size_t)h * 32 + w0;
    #pragma unroll 4
    for (int i = tid; i < 16 * NCODE; i += 512) {
        int n = i >> 4, w = i & 15;
        float x = lg[(size_t)n * 1024 + w];
        float e = __expf(-fabsf(x));
        float sp = fmaxf(x, 0.f) + __logf(1.f + e);
        alpha_t[w * PXS + n] = sp + 1.f;
    }
    __syncthreads();

    const int warp = tid >> 5, lane = tid & 31;      // warp = pixel-in-block
    const int p = b * 1024 + h * 32 + w0 + warp;     // global pixel index
    float* row = alpha_t + warp * PXS;
    const float* nz = noise + (size_t)p * NCODE;

    // Pass 1: KL sums, t2 = (a/(-log u))^2, Z = sum t2, argmax t2
    float S = 0.f, slg = 0.f, sdg = 0.f, Z = 0.f, m = -1.f;
    int bi = 0;
    #pragma unroll 1
    for (int ko = 0; ko < 8; ko++) {
        float P = 1.f;
        #pragma unroll
        for (int kj = 0; kj < 4; kj++) {
            int n = (ko * 4 + kj) * 32 + lane;
            float a = row[n];
            float prod = a * (a + 1.f);
            float x2   = a + 2.f;
            float invall = __fdividef(1.f, prod * x2);
            float inv  = invall * prod;      // 1/(x+2)
            float invp = invall * x2;        // 1/(x(x+1))
            float lx   = __logf(x2);
            float inv2 = inv * inv;
            float lga = (x2 - 0.5f) * lx - x2 + 0.9189385332046727f
                      + inv * (0.083333333333f - inv2 * 2.7777777778e-3f);
            float psa = lx - 0.5f * inv
                      - inv2 * (0.083333333333f - inv2 * 8.3333333333e-3f)
                      - (2.f * a + 1.f) * invp;
            P *= prod;                        // batched -log(prod)
            S += a; slg += lga; sdg += (a - 1.f) * psa;
            float L = -__logf(nz[n]);
            float t = __fdividef(a, L);
            float t2 = t * t;
            row[n] = t2;
            Z += t2;
            if (t2 > m) { m = t2; bi = n; }
        }
        slg -= __logf(P);
    }
    #pragma unroll
    for (int o = 16; o; o >>= 1) {
        S   += __shfl_xor_sync(0xffffffffu, S, o);
        slg += __shfl_xor_sync(0xffffffffu, slg, o);
        sdg += __shfl_xor_sync(0xffffffffu, sdg, o);
        Z   += __shfl_xor_sync(0xffffffffu, Z, o);
        float mo = __shfl_xor_sync(0xffffffffu, m, o);
        int   bo = __shfl_xor_sync(0xffffffffu, bi, o);
        if (mo > m || (mo == m && bo < bi)) { m = mo; bi = bo; }
    }
    float invZ = __fdividef(1.f, Z);

    // Pass 2: normalized sample -> fp16 global + fp32 smem (for column sums)
    __half* srow = g_sampleH + (size_t)p * NCODE;
    #pragma unroll 4
    for (int k = 0; k < 32; k++) {
        int n = k * 32 + lane;
        float s = row[n] * invZ;
        row[n] = s;
        srow[n] = __float2half_rn(s);
    }

    if (lane == 0) {
        float lgS, psS, lgN, psN;
        lgamma_digamma(S, lgS, psS);
        lgamma_digamma(1024.f, lgN, psN);
        float kl = lgS - slg - lgN + sdg - (S - 1024.f) * psS;
        atomicAdd(&g_kl, kl);
        out[IDX_OFF + p] = (float)bi;
    }
    __syncthreads();

    // Column sums over the 16 pixels -> one atomic per code per block
    #pragma unroll
    for (int c = tid; c < NCODE; c += 512) {
        float acc = 0.f;
        #pragma unroll
        for (int w = 0; w < 16; w++) acc += alpha_t[w * PXS + c];
        atomicAdd(&g_avg[c], acc);
    }
}

// ---------------------------------------------------------------- fp16 mma GEMM
// (exact R10 configuration: K-tile 32, 3-stage cp.async, both barriers)
#define KT        32
#define ROWB      80                       // bytes per smem row
#define STG_BYTES (128 * ROWB)             // 10240 per operand per stage
#define GEMM_SMEM (6 * STG_BYTES)          // 61440

__device__ __forceinline__ void gemm_issue(uint32_t Ab, uint32_t Bb,
                                           const __half* arow, const __half* brow,
                                           int k0, int tid) {
    const int row = tid >> 1, c0 = (tid & 1) * 2;     // 2 chunks each of A,B
    #pragma unroll
    for (int j = 0; j < 2; j++) {
        cpa16(Ab + row * ROWB + (c0 + j) * 16, arow + (size_t)row * NCODE + k0 + (c0 + j) * 8);
        cpa16(Bb + row * ROWB + (c0 + j) * 16, brow + (size_t)row * NCODE + k0 + (c0 + j) * 8);
    }
    asm volatile("cp.async.commit_group;" ::: "memory");
}

__global__ __launch_bounds__(256, 2) void gemm_mma(float* __restrict__ out) {
    extern __shared__ __align__(16) char gsm[];
    const uint32_t base = smem_u32(gsm);

    const int tid = threadIdx.x, warp = tid >> 5, lane = tid & 31;
    const int gid = lane >> 2, tig = lane & 3;
    const int wm = warp >> 2, wn = warp & 3;
    const int p0 = blockIdx.x * 128, d0 = blockIdx.y * 128;

    const __half* arow = g_cbH + (size_t)d0 * NCODE;
    const __half* brow = g_sampleH + (size_t)p0 * NCODE;

    // lane-fixed ldmatrix address components
    const uint32_t a_lrow = (uint32_t)(wm * 64 + (lane & 15)) * ROWB + ((lane >> 4) & 1) * 16;
    const uint32_t b_lrow = (uint32_t)(wn * 32 + ((lane >> 4) & 1) * 8 + (lane & 7)) * ROWB
                          + ((lane >> 3) & 1) * 16;

    gemm_issue(base, base + 3 * STG_BYTES, arow, brow, 0, tid);
    gemm_issue(base + STG_BYTES, base + 4 * STG_BYTES, arow, brow, KT, tid);

    float acc[4][4][4] = {};

    for (int c = 0; c < 32; c++) {
        const int buf = c % 3;
        if (c < 30) asm volatile("cp.async.wait_group 1;" ::: "memory");
        else        asm volatile("cp.async.wait_group 0;" ::: "memory");
        __syncthreads();
        if (c + 2 < 32) {
            const int nb = (c + 2) % 3;
            gemm_issue(base + nb * STG_BYTES, base + (3 + nb) * STG_BYTES,
                       arow, brow, (c + 2) * KT, tid);
        }

        const uint32_t Ab = base + buf * STG_BYTES + a_lrow;
        const uint32_t Bb = base + (3 + buf) * STG_BYTES + b_lrow;
        #pragma unroll
        for (int sk = 0; sk < 2; sk++) {
            const uint32_t ko = sk * 32;
            uint32_t afr[4][4], bfr[4][2];
            #pragma unroll
            for (int mf = 0; mf < 4; mf++)
                ldsm4(afr[mf], Ab + mf * (16 * ROWB) + ko);
            #pragma unroll
            for (int np = 0; np < 2; np++) {
                uint32_t r[4];
                ldsm4(r, Bb + np * (16 * ROWB) + ko);
                bfr[2 * np][0] = r[0]; bfr[2 * np][1] = r[1];
                bfr[2 * np + 1][0] = r[2]; bfr[2 * np + 1][1] = r[3];
            }
            #pragma unroll
            for (int mf = 0; mf < 4; mf++)
                #pragma unroll
                for (int nf = 0; nf < 4; nf++)
                    mma_f16(acc[mf][nf], afr[mf], bfr[nf]);
        }
        __syncthreads();
    }

    const int bimg = p0 >> 10, hwb = p0 & 1023;
    #pragma unroll
    for (int mf = 0; mf < 4; mf++) {
        const int d = d0 + wm * 64 + mf * 16 + gid;
        float* orow = out + (size_t)bimg * (DDIM * 1024) + (size_t)d * 1024 + hwb;
        #pragma unroll
        for (int nf = 0; nf < 4; nf++) {
            const int col = wn * 32 + nf * 8 + 2 * tig;
            *(float2*)&orow[col]            = make_float2(acc[mf][nf][0], acc[mf][nf][1]);
            *(float2*)&orow[col + 8 * 1024] = make_float2(acc[mf][nf][2], acc[mf][nf][3]);
        }
    }

    // Fused finalize: g_avg/g_kl complete (pixel_kernel precedes this kernel).
    // After reading, reset them to preserve the zero-on-entry invariant.
    if (blockIdx.x == 0 && blockIdx.y == 0) {
        __shared__ float red[8];
        float hs = 0.f;
        #pragma unroll
        for (int j = 0; j < 4; j++) {
            float v = g_avg[tid * 4 + j] * (1.f / 16384.f);
            hs += v * __logf(v + 1e-10f);
        }
        *(float4*)&g_avg[tid * 4] = make_float4(0.f, 0.f, 0.f, 0.f);  // reset
        #pragma unroll
        for (int o = 16; o; o >>= 1) hs += __shfl_xor_sync(0xffffffffu, hs, o);
        if (lane == 0) red[warp] = hs;
        __syncthreads();
        if (tid == 0) {
            float s = 0.f;
            #pragma unroll
            for (int wq = 0; wq < 8; wq++) s += red[wq];
            out[PERP_OFF] = __expf(-s);
            out[KL_OFF] = (1e-3f / 16384.f) * g_kl;
            g_kl = 0.f;                                               // reset
        }
    }
}

// ---------------------------------------------------------------- launch
extern "C" void kernel_launch(void* const* d_in, const int* in_sizes, int n_in,
                              void* d_out, int out_size) {
    const float* logits = (const float*)d_in[0];
    const float* cb     = (const float*)d_in[1];
    const float* noise  = (const float*)d_in[2];
    float* out = (float*)d_out;

    const int px_smem = 16 * PXS * 4;
    cudaFuncSetAttribute(pixel_kernel,
                         cudaFuncAttributeMaxDynamicSharedMemorySize, px_smem);
    cudaFuncSetAttribute(gemm_mma,
                         cudaFuncAttributeMaxDynamicSharedMemorySize, GEMM_SMEM);

    pixel_kernel<<<1024, 512, px_smem>>>(logits, noise, cb, out);
    gemm_mma<<<dim3(NPIX / 128, DDIM / 128), 256, GEMM_SMEM>>>(out);
}

// round 17
// speedup vs baseline: 1.1675x; 1.1582x over previous
#include <cuda_runtime.h>
#include <cuda_fp16.h>
#include <cstdint>

// Problem constants
#define NPIX   16384            // B*H*W
#define NCODE  1024             // N (= K of the GEMM)
#define DDIM   256              // D (= M of the GEMM)
#define ZQ_SIZE 4194304         // B*D*H*W
#define KL_OFF  ZQ_SIZE
#define IDX_OFF (ZQ_SIZE + 1)
#define PERP_OFF (ZQ_SIZE + 1 + NPIX)

// Static device scratch (no allocation allowed).
// INVARIANT: g_avg / g_kl are zero at kernel_launch entry; the gemm finalize
// resets them after reading, so every execution restores the invariant.
__device__ __half g_sampleH[(size_t)NPIX * NCODE];  // 32 MB, [pixel][k]
__device__ __half g_cbH[(size_t)DDIM * NCODE];      // 512 KB, [d][k] (transposed)
__device__ float g_avg[NCODE];
__device__ float g_kl;

// ---------------------------------------------------------------- helpers
__device__ __forceinline__ uint32_t smem_u32(const void* p) {
    uint32_t a;
    asm("{ .reg .u64 t; cvta.to.shared.u64 t, %1; cvt.u32.u64 %0, t; }" : "=r"(a) : "l"(p));
    return a;
}
__device__ __forceinline__ void cpa16(uint32_t d, const void* s) {
    asm volatile("cp.async.cg.shared.global [%0], [%1], 16;" :: "r"(d), "l"(s));
}
__device__ __forceinline__ void ldsm4(uint32_t* r, uint32_t a) {
    asm volatile("ldmatrix.sync.aligned.m8n8.x4.shared.b16 {%0,%1,%2,%3}, [%4];"
                 : "=r"(r[0]), "=r"(r[1]), "=r"(r[2]), "=r"(r[3]) : "r"(a));
}
__device__ __forceinline__ void mma_f16(float* c, const uint32_t* a, const uint32_t* b) {
    asm volatile(
        "mma.sync.aligned.m16n8k16.row.col.f32.f16.f16.f32 "
        "{%0,%1,%2,%3}, {%4,%5,%6,%7}, {%8,%9}, {%0,%1,%2,%3};"
        : "+f"(c[0]), "+f"(c[1]), "+f"(c[2]), "+f"(c[3])
        : "r"(a[0]), "r"(a[1]), "r"(a[2]), "r"(a[3]), "r"(b[0]), "r"(b[1]));
}
__device__ __forceinline__ void st_streaming_u32(__half* p, uint32_t v) {
    asm volatile("st.global.cs.b32 [%0], %1;" :: "l"(p), "r"(v) : "memory");
}

// Branch-free fused lgamma + digamma for x >= 1 (double shift + Stirling at x+2).
// Single MUFU reciprocal; trimmed series (err < 6e-6 at x2 >= 3).
__device__ __forceinline__ void lgamma_digamma(float x, float& lg, float& ps) {
    float prod = x * (x + 1.f);
    float x2   = x + 2.f;
    float invall = __fdividef(1.f, prod * x2);
    float inv  = invall * prod;      // 1/(x+2)
    float invp = invall * x2;        // 1/(x(x+1))
    float lx   = __logf(x2);
    float inv2 = inv * inv;
    lg = (x2 - 0.5f) * lx - x2 + 0.9189385332046727f
       + inv * (0.083333333333f - inv2 * 2.7777777778e-3f)
       - __logf(prod);
    ps = lx - 0.5f * inv
       - inv2 * (0.083333333333f - inv2 * 8.3333333333e-3f)
       - (2.f * x + 1.f) * invp;
}

// ---------------------------------------------------------------- per-pixel pass
// (exact R10 body + streaming cache hints on the read-once/write-once streams)
// 1024 blocks x 512 threads. Block = 16 pixels.
// Blocks 0..255 first transpose one 32x32 codebook tile.
// t = alpha/(-log u); softmax(T=0.5) == t^2 / sum t^2; argmax(t) == argmax.
#define PXS 1025
extern __shared__ float smem_dyn[];
__global__ __launch_bounds__(512) void pixel_kernel(
    const float* __restrict__ logits,
    const float* __restrict__ noise,
    const float* __restrict__ cb,
    float* __restrict__ out)
{
    float* alpha_t = smem_dyn;              // [16][PXS]
    const int tid = threadIdx.x;
    const int blk = blockIdx.x;             // b*64 + h*2 + half
    const int b = blk >> 6, h = (blk >> 1) & 31, half = blk & 1;
    const int w0 = half * 16;

    // Codebook transpose pre-phase (blocks 0..255, one 32x32 tile each)
    if (blk < 256) {
        float (*tt)[33] = (float(*)[33])smem_dyn;
        const int n0 = (blk & 31) * 32, d0 = (blk >> 5) * 32;
        const int x = tid & 31, y = tid >> 5;       // y in 0..15
        #pragma unroll
        for (int j = 0; j < 2; j++) {
            int r = y + j * 16;
            tt[r][x] = cb[(size_t)(n0 + r) * DDIM + d0 + x];
        }
        __syncthreads();
        #pragma unroll
        for (int j = 0; j < 2; j++) {
            int r = y + j * 16;
            g_cbH[(size_t)(d0 + r) * NCODE + n0 + x] = __float2half_rn(tt[x][r]);
        }
        __syncthreads();
    }

    // Stage: softplus(logits)+1, transposed to [w][n]
    const float* lg = logits + (size_t)b * (NCODE * 1024) + (size_t)h * 32 + w0;
    #pragma unroll 4
    for (int i = tid; i < 16 * NCODE; i += 512) {
        int n = i >> 4, w = i & 15;
        float x = __ldcs(&lg[(size_t)n * 1024 + w]);
        float e = __expf(-fabsf(x));
        float sp = fmaxf(x, 0.f) + __logf(1.f + e);
        alpha_t[w * PXS + n] = sp + 1.f;
    }
    __syncthreads();

    const int warp = tid >> 5, lane = tid & 31;      // warp = pixel-in-block
    const int p = b * 1024 + h * 32 + w0 + warp;     // global pixel index
    float* row = alpha_t + warp * PXS;
    const float* nz = noise + (size_t)p * NCODE;

    // Pass 1: KL sums, t = a / (-log u), Z = sum t^2, argmax t
    float S = 0.f, slg = 0.f, sdg = 0.f, Z = 0.f, m = -1.f;
    int bi = 0;
    #pragma unroll 4
    for (int k = 0; k < 32; k++) {
        int n = k * 32 + lane;
        float a = row[n];
        float lga, psa;
        lgamma_digamma(a, lga, psa);
        S += a; slg += lga; sdg += (a - 1.f) * psa;
        float L = -__logf(__ldcs(&nz[n]));
        float t = __fdividef(a, L);
        row[n] = t;
        Z += t * t;
        if (t > m) { m = t; bi = n; }
    }
    #pragma unroll
    for (int o = 16; o; o >>= 1) {
        S   += __shfl_xor_sync(0xffffffffu, S, o);
        slg += __shfl_xor_sync(0xffffffffu, slg, o);
        sdg += __shfl_xor_sync(0xffffffffu, sdg, o);
        Z   += __shfl_xor_sync(0xffffffffu, Z, o);
        float mo = __shfl_xor_sync(0xffffffffu, m, o);
        int   bo = __shfl_xor_sync(0xffffffffu, bi, o);
        if (mo > m || (mo == m && bo < bi)) { m = mo; bi = bo; }
    }
    float invZ = __fdividef(1.f, Z);

    // Pass 2: normalized sample -> fp16 global (streaming) + fp32 smem
    __half* srow = g_sampleH + (size_t)p * NCODE;
    #pragma unroll 4
    for (int k = 0; k < 16; k++) {
        int n = k * 64 + lane * 2;
        float t0 = row[n], t1 = row[n + 1];
        float s0 = t0 * t0 * invZ, s1 = t1 * t1 * invZ;
        row[n] = s0; row[n + 1] = s1;
        __half2 hh = __floats2half2_rn(s0, s1);
        st_streaming_u32(srow + n, *(uint32_t*)&hh);
    }

    if (lane == 0) {
        float lgS, psS, lgN, psN;
        lgamma_digamma(S, lgS, psS);
        lgamma_digamma(1024.f, lgN, psN);
        float kl = lgS - slg - lgN + sdg - (S - 1024.f) * psS;
        atomicAdd(&g_kl, kl);
        out[IDX_OFF + p] = (float)bi;
    }
    __syncthreads();

    // Column sums over the 16 pixels -> one atomic per code per block
    #pragma unroll
    for (int c = tid; c < NCODE; c += 512) {
        float acc = 0.f;
        #pragma unroll
        for (int w = 0; w < 16; w++) acc += alpha_t[w * PXS + c];
        atomicAdd(&g_avg[c], acc);
    }
}

// ---------------------------------------------------------------- fp16 mma GEMM
// (exact R10 configuration: K-tile 32, 3-stage cp.async, both barriers)
// Grid is launched d-fastest: the two co-resident CTAs on an SM share the same
// B (sample) tile, so the second CTA's B stream hits L2.
#define KT        32
#define ROWB      80                       // bytes per smem row
#define STG_BYTES (128 * ROWB)             // 10240 per operand per stage
#define GEMM_SMEM (6 * STG_BYTES)          // 61440

__device__ __forceinline__ void gemm_issue(uint32_t Ab, uint32_t Bb,
                                           const __half* arow, const __half* brow,
                                           int k0, int tid) {
    const int row = tid >> 1, c0 = (tid & 1) * 2;     // 2 chunks each of A,B
    #pragma unroll
    for (int j = 0; j < 2; j++) {
        cpa16(Ab + row * ROWB + (c0 + j) * 16, arow + (size_t)row * NCODE + k0 + (c0 + j) * 8);
        cpa16(Bb + row * ROWB + (c0 + j) * 16, brow + (size_t)row * NCODE + k0 + (c0 + j) * 8);
    }
    asm volatile("cp.async.commit_group;" ::: "memory");
}

__global__ __launch_bounds__(256, 2) void gemm_mma(float* __restrict__ out) {
    extern __shared__ __align__(16) char gsm[];
    const uint32_t base = smem_u32(gsm);

    const int tid = threadIdx.x, warp = tid >> 5, lane = tid & 31;
    const int gid = lane >> 2, tig = lane & 3;
    const int wm = warp >> 2, wn = warp & 3;
    const int p0 = blockIdx.y * 128, d0 = blockIdx.x * 128;   // d-fastest ordering

    const __half* arow = g_cbH + (size_t)d0 * NCODE;
    const __half* brow = g_sampleH + (size_t)p0 * NCODE;

    // lane-fixed ldmatrix address components
    const uint32_t a_lrow = (uint32_t)(wm * 64 + (lane & 15)) * ROWB + ((lane >> 4) & 1) * 16;
    const uint32_t b_lrow = (uint32_t)(wn * 32 + ((lane >> 4) & 1) * 8 + (lane & 7)) * ROWB
                          + ((lane >> 3) & 1) * 16;

    gemm_issue(base, base + 3 * STG_BYTES, arow, brow, 0, tid);
    gemm_issue(base + STG_BYTES, base + 4 * STG_BYTES, arow, brow, KT, tid);

    float acc[4][4][4] = {};

    for (int c = 0; c < 32; c++) {
        const int buf = c % 3;
        if (c < 30) asm volatile("cp.async.wait_group 1;" ::: "memory");
        else        asm volatile("cp.async.wait_group 0;" ::: "memory");
        __syncthreads();
        if (c + 2 < 32) {
            const int nb = (c + 2) % 3;
            gemm_issue(base + nb * STG_BYTES, base + (3 + nb) * STG_BYTES,
                       arow, brow, (c + 2) * KT, tid);
        }

        const uint32_t Ab = base + buf * STG_BYTES + a_lrow;
        const uint32_t Bb = base + (3 + buf) * STG_BYTES + b_lrow;
        #pragma unroll
        for (int sk = 0; sk < 2; sk++) {
            const uint32_t ko = sk * 32;
            uint32_t afr[4][4], bfr[4][2];
            #pragma unroll
            for (int mf = 0; mf < 4; mf++)
                ldsm4(afr[mf], Ab + mf * (16 * ROWB) + ko);
            #pragma unroll
            for (int np = 0; np < 2; np++) {
                uint32_t r[4];
                ldsm4(r, Bb + np * (16 * ROWB) + ko);
                bfr[2 * np][0] = r[0]; bfr[2 * np][1] = r[1];
                bfr[2 * np + 1][0] = r[2]; bfr[2 * np + 1][1] = r[3];
            }
            #pragma unroll
            for (int mf = 0; mf < 4; mf++)
                #pragma unroll
                for (int nf = 0; nf < 4; nf++)
                    mma_f16(acc[mf][nf], afr[mf], bfr[nf]);
        }
        __syncthreads();
    }

    const int bimg = p0 >> 10, hwb = p0 & 1023;
    #pragma unroll
    for (int mf = 0; mf < 4; mf++) {
        const int d = d0 + wm * 64 + mf * 16 + gid;
        float* orow = out + (size_t)bimg * (DDIM * 1024) + (size_t)d * 1024 + hwb;
        #pragma unroll
        for (int nf = 0; nf < 4; nf++) {
            const int col = wn * 32 + nf * 8 + 2 * tig;
            *(float2*)&orow[col]            = make_float2(acc[mf][nf][0], acc[mf][nf][1]);
            *(float2*)&orow[col + 8 * 1024] = make_float2(acc[mf][nf][2], acc[mf][nf][3]);
        }
    }

    // Fused finalize: g_avg/g_kl complete (pixel_kernel precedes this kernel).
    // After reading, reset them to preserve the zero-on-entry invariant.
    if (blockIdx.x == 0 && blockIdx.y == 0) {
        __shared__ float red[8];
        float hs = 0.f;
        #pragma unroll
        for (int j = 0; j < 4; j++) {
            float v = g_avg[tid * 4 + j] * (1.f / 16384.f);
            hs += v * __logf(v + 1e-10f);
        }
        *(float4*)&g_avg[tid * 4] = make_float4(0.f, 0.f, 0.f, 0.f);  // reset
        #pragma unroll
        for (int o = 16; o; o >>= 1) hs += __shfl_xor_sync(0xffffffffu, hs, o);
        if (lane == 0) red[warp] = hs;
        __syncthreads();
        if (tid == 0) {
            float s = 0.f;
            #pragma unroll
            for (int wq = 0; wq < 8; wq++) s += red[wq];
            out[PERP_OFF] = __expf(-s);
            out[KL_OFF] = (1e-3f / 16384.f) * g_kl;
            g_kl = 0.f;                                               // reset
        }
    }
}

// ---------------------------------------------------------------- launch
extern "C" void kernel_launch(void* const* d_in, const int* in_sizes, int n_in,
                              void* d_out, int out_size) {
    const float* logits = (const float*)d_in[0];
    const float* cb     = (const float*)d_in[1];
    const float* noise  = (const float*)d_in[2];
    float* out = (float*)d_out;

    const int px_smem = 16 * PXS * 4;
    cudaFuncSetAttribute(pixel_kernel,
                         cudaFuncAttributeMaxDynamicSharedMemorySize, px_smem);
    cudaFuncSetAttribute(gemm_mma,
                         cudaFuncAttributeMaxDynamicSharedMemorySize, GEMM_SMEM);

    pixel_kernel<<<1024, 512, px_smem>>>(logits, noise, cb, out);
    gemm_mma<<<dim3(DDIM / 128, NPIX / 128), 256, GEMM_SMEM>>>(out);   // d-fastest
}